// round 17
// baseline (speedup 1.0000x reference)
#include <cuda_runtime.h>
#include <cstdint>

// Problem constants
#define Bn 4
#define Cn 32
#define Ln 256
#define Mn 256
#define Fn 8
#define Nw 64
#define LM (Ln * Mn)
#define IMAG_OFF ((size_t)Bn * Fn * LM)

__device__ __forceinline__ uint32_t cvt_tf32(float x) {
    uint32_t r;
    asm("cvt.rna.tf32.f32 %0, %1;" : "=r"(r) : "f"(x));
    return r;
}

__device__ __forceinline__ void mma_tf32(float* d, const uint32_t* a,
                                         const uint32_t* b) {
    asm("mma.sync.aligned.m16n8k8.row.col.f32.tf32.tf32.f32 "
        "{%0,%1,%2,%3}, {%4,%5,%6,%7}, {%8,%9}, {%0,%1,%2,%3};"
        : "+f"(d[0]), "+f"(d[1]), "+f"(d[2]), "+f"(d[3])
        : "r"(a[0]), "r"(a[1]), "r"(a[2]), "r"(a[3]), "r"(b[0]), "r"(b[1]));
}

// ---------------------------------------------------------------------------
// Grid: B*L = 1024 CTAs, 256 threads (8 warps). CTA = one (b, l).
// Warp w owns m-stripe [w*32, w*32+32): 2 m16 tiles x 2 n8 tiles x 4 k8 tiles.
// D[256x16] = Xr * B1 + Xi * B2,  B1 = [wr | wi], B2 = [-wi | wr] (tf32).
// A-fragments straight from global (coalesced 32B sectors); B from 4KB smem.
// k-tiles double-buffered (prefetch distance 1); batch-0 issued before interp.
// ---------------------------------------------------------------------------
__global__ __launch_bounds__(256, 3) void sphere_mma_kernel(
    const float* __restrict__ xr,
    const float* __restrict__ xi,
    const float* __restrict__ wr,
    const float* __restrict__ wi,
    float* __restrict__ out) {
    __shared__ float B1[Cn][16];   // [c][n]: n<8 -> wr[f=n], n>=8 -> wi[f=n-8]
    __shared__ float B2[Cn][16];   // [c][n]: n<8 -> -wi[n],  n>=8 -> wr[n-8]

    int bid = blockIdx.x;
    int b = bid >> 8;
    int l = bid & (Ln - 1);
    int tid = threadIdx.x;
    int wid = tid >> 5;
    int lane = tid & 31;
    int g = lane >> 2;       // group id (row within tile)
    int q = lane & 3;        // thread in group (col within k)

    int mbase = wid * 32 + g;
    const float* pxr = xr + (size_t)b * Cn * LM + (size_t)l * Mn;
    const float* pxi = xi + (size_t)b * Cn * LM + (size_t)l * Mn;

    // fragment element coords: (mt, jj): m = mbase + mt*16 + (jj&1)*8,
    //                                    c = q + kt*8 + (jj>>1)*4
    // ---- prologue: issue kt=0 loads BEFORE weight interp ----
    float bufR[2][8], bufI[2][8];
#pragma unroll
    for (int mt = 0; mt < 2; ++mt)
#pragma unroll
        for (int jj = 0; jj < 4; ++jj) {
            int m = mbase + mt * 16 + (jj & 1) * 8;
            int c = q + (jj >> 1) * 4;
            bufR[0][mt * 4 + jj] = __ldg(pxr + (size_t)c * LM + m);
            bufI[0][mt * 4 + jj] = __ldg(pxi + (size_t)c * LM + m);
        }

    // ---- weight interp -> tf32 -> smem B tiles (1 (f,c) per thread) ----
    {
        float t = (float)l * (63.0f / 255.0f);
        int lo = (int)t;
        if (lo > Nw - 2) lo = Nw - 2;
        float fr = t - (float)lo;
        float om = 1.0f - fr;
        int k = tid;                 // k = f*Cn + c, covers 256 exactly
        int f = k >> 5;
        int c = k & 31;
        const float* pwr = wr + k * Nw + lo;
        const float* pwi = wi + k * Nw + lo;
        float vr = pwr[0] * om + pwr[1] * fr;
        float vi = pwi[0] * om + pwi[1] * fr;
        float vrt = __uint_as_float(cvt_tf32(vr));
        float vit = __uint_as_float(cvt_tf32(vi));
        B1[c][f] = vrt;
        B1[c][8 + f] = vit;
        B2[c][f] = -vit;
        B2[c][8 + f] = vrt;
    }
    __syncthreads();

    float acc[2][2][4];
#pragma unroll
    for (int mt = 0; mt < 2; ++mt)
#pragma unroll
        for (int nt = 0; nt < 2; ++nt)
#pragma unroll
            for (int j = 0; j < 4; ++j) acc[mt][nt][j] = 0.0f;

#pragma unroll
    for (int kt = 0; kt < 4; ++kt) {
        int cur = kt & 1;
        // prefetch next k-tile's A fragments
        if (kt < 3) {
            int nxt = cur ^ 1;
#pragma unroll
            for (int mt = 0; mt < 2; ++mt)
#pragma unroll
                for (int jj = 0; jj < 4; ++jj) {
                    int m = mbase + mt * 16 + (jj & 1) * 8;
                    int c = q + (kt + 1) * 8 + (jj >> 1) * 4;
                    bufR[nxt][mt * 4 + jj] = __ldg(pxr + (size_t)c * LM + m);
                    bufI[nxt][mt * 4 + jj] = __ldg(pxi + (size_t)c * LM + m);
                }
        }

        // convert current to tf32
        uint32_t Ar[2][4], Ai[2][4];
#pragma unroll
        for (int mt = 0; mt < 2; ++mt)
#pragma unroll
            for (int jj = 0; jj < 4; ++jj) {
                Ar[mt][jj] = cvt_tf32(bufR[cur][mt * 4 + jj]);
                Ai[mt][jj] = cvt_tf32(bufI[cur][mt * 4 + jj]);
            }

        // B fragments from smem: b0 row = q, b1 row = q+4 (within k-tile)
        uint32_t b1f[2][2], b2f[2][2];
#pragma unroll
        for (int nt = 0; nt < 2; ++nt) {
            int n = g + nt * 8;
            int c0 = kt * 8 + q;
            b1f[nt][0] = __float_as_uint(B1[c0][n]);
            b1f[nt][1] = __float_as_uint(B1[c0 + 4][n]);
            b2f[nt][0] = __float_as_uint(B2[c0][n]);
            b2f[nt][1] = __float_as_uint(B2[c0 + 4][n]);
        }

#pragma unroll
        for (int mt = 0; mt < 2; ++mt)
#pragma unroll
            for (int nt = 0; nt < 2; ++nt) {
                mma_tf32(acc[mt][nt], Ar[mt], b1f[nt]);
                mma_tf32(acc[mt][nt], Ai[mt], b2f[nt]);
            }
    }

    // ---- epilogue: scale, relu (real), store ----
    float sc = sqrtf(1.0f + (float)l) * (1.0f / 32.0f);
    float* obase = out + (size_t)b * Fn * LM + (size_t)l * Mn;

#pragma unroll
    for (int mt = 0; mt < 2; ++mt) {
#pragma unroll
        for (int nt = 0; nt < 2; ++nt) {
#pragma unroll
            for (int j = 0; j < 4; ++j) {
                int row = mbase + mt * 16 + (j >> 1) * 8;   // m
                int col = 2 * q + (j & 1) + nt * 8;         // D column
                float v = acc[mt][nt][j] * sc;
                if (nt == 0) {
                    // real part, f = col, relu
                    obase[(size_t)col * LM + row] = fmaxf(v, 0.0f);
                } else {
                    // imag part, f = col - 8
                    obase[IMAG_OFF + (size_t)(col - 8) * LM + row] = v;
                }
            }
        }
    }
}

extern "C" void kernel_launch(void* const* d_in, const int* in_sizes, int n_in,
                              void* d_out, int out_size) {
    const float* x_real = (const float*)d_in[0];
    const float* x_imag = (const float*)d_in[1];
    const float* w_real = (const float*)d_in[2];
    const float* w_imag = (const float*)d_in[3];
    float* out = (float*)d_out;

    sphere_mma_kernel<<<Bn * Ln, 256>>>(x_real, x_imag, w_real, w_imag, out);
}